// round 5
// baseline (speedup 1.0000x reference)
#include <cuda_runtime.h>
#include <cuda_bf16.h>
#include <cstdint>

// Problem constants
#define N        8192
#define IN_DIM   512
#define NCLASS   16
#define PC       512      // per class
#define KK       256      // kept per class
#define NSEL     4096     // NCLASS * KK

// Output layout (single f32 buffer): M_out | X_out | mask_out
#define M_OUT_OFF    0
#define X_OUT_OFF    (NSEL * (size_t)NSEL)               // 16777216
#define MASK_OUT_OFF (X_OUT_OFF + NSEL * (size_t)IN_DIM) // 18874368

// Scratch (device globals — no allocation allowed)
__device__ float g_scores[N];
__device__ int   g_idx[NSEL];
__device__ float g_vals[NSEL];
__device__ int   g_is64;

// ---------------------------------------------------------------------------
// Kernel 0: detect whether mask came through as int64 (odd int32 words all 0)
// ---------------------------------------------------------------------------
__global__ void detect_mask_kernel(const int* __restrict__ m) {
    int all0 = 1;
    for (int t = 1; t < 256; t += 2) {
        if (m[t] != 0) { all0 = 0; break; }
    }
    g_is64 = all0;
}

// ---------------------------------------------------------------------------
// Bit-replica of XLA:CPU / Eigen Cephes expf (GenerateVF32Exp / pexp_float).
// All mul/add explicitly rounded or fused exactly as the LLVM IR emits them
// (fmuladd -> NEON fmla on the Grace host). For |r| < 0.35, fx == 0 and the
// range-reduction terms vanish exactly, leaving the pure polynomial.
// ---------------------------------------------------------------------------
__device__ __forceinline__ float cephes_expf(float r) {
    float in = fminf(fmaxf(r, -88.3762626647949f), 88.3762626647950f);
    float fx = floorf(__fmaf_rn(in, 1.44269504088896341f, 0.5f));
    float tmp = __fmul_rn(0.693359375f, fx);
    float zz  = __fmul_rn(-2.12194440e-4f, fx);
    float x   = __fsub_rn(__fsub_rn(in, tmp), zz);
    float z2  = __fmul_rn(x, x);
    float y   = __fmaf_rn(x, 1.9875691500E-4f, 1.3981999507E-3f);
    y = __fmaf_rn(y, x, 8.3334519073E-3f);
    y = __fmaf_rn(y, x, 4.1665795894E-2f);
    y = __fmaf_rn(y, x, 1.6666665459E-1f);
    y = __fmaf_rn(y, x, 5.0000001201E-1f);
    y = __fmaf_rn(y, z2, x);
    y = __fadd_rn(1.0f, y);
    int n = (int)fx;
    float pow2n = __int_as_float((unsigned)(n + 127) << 23);
    return __fmul_rn(y, pow2n);
}

// ---------------------------------------------------------------------------
// Kernel 1: scores[i] = 1 / (1 + exp(-((X[i,:]·W + b) / 100)))
// Dot order is provably irrelevant at score precision; sigma must be
// bit-exact vs XLA:CPU -> Cephes expf above. One warp per row.
// ---------------------------------------------------------------------------
__global__ void score_kernel(const float* __restrict__ X,
                             const float* __restrict__ W,
                             const float* __restrict__ b) {
    int warps_per_block = blockDim.x >> 5;
    int row  = blockIdx.x * warps_per_block + (threadIdx.x >> 5);
    int lane = threadIdx.x & 31;
    if (row >= N) return;
    const float* xr = X + (size_t)row * IN_DIM;
    float s = 0.f;
#pragma unroll
    for (int k = lane; k < IN_DIM; k += 32)
        s = __fmaf_rn(xr[k], __ldg(&W[k]), s);
#pragma unroll
    for (int o = 16; o > 0; o >>= 1)
        s += __shfl_xor_sync(0xffffffffu, s, o);
    if (lane == 0) {
        float x = __fdiv_rn(__fadd_rn(s, b[0]), 100.0f);
        float t = cephes_expf(-x);
        g_scores[row] = __fdiv_rn(1.0f, __fadd_rn(1.0f, t));
    }
}

// ---------------------------------------------------------------------------
// Kernel 2: per-class collection (order-preserving scan) + bitonic sort 512,
// keep the 256 smallest scores (ascending; ties -> lower index first).
// One block per class, 512 threads.
// ---------------------------------------------------------------------------
__global__ void select_kernel(const int* __restrict__ mask_i32,
                              float* __restrict__ out) {
    __shared__ unsigned long long keys[PC];
    __shared__ int scan[PC];
    __shared__ int base_s;

    const int j   = blockIdx.x;
    const int tid = threadIdx.x;
    const int is64 = g_is64;

    if (tid == 0) base_s = 0;
    __syncthreads();

    for (int round = 0; round < N / PC; ++round) {
        int i = round * PC + tid;
        int cls = is64 ? mask_i32[2 * i] : mask_i32[i];
        int flag = (cls == j) ? 1 : 0;
        scan[tid] = flag;
        __syncthreads();
        for (int off = 1; off < PC; off <<= 1) {
            int v = (tid >= off) ? scan[tid - off] : 0;
            __syncthreads();
            scan[tid] += v;
            __syncthreads();
        }
        if (flag) {
            int pos = base_s + scan[tid] - 1;
            unsigned sb = __float_as_uint(g_scores[i]);  // (0,1): bit order == value order
            keys[pos] = ((unsigned long long)sb << 32) | (unsigned)i;
        }
        __syncthreads();
        if (tid == 0) base_s += scan[PC - 1];
        __syncthreads();
    }

    // Bitonic sort ascending (512 elements, 512 threads)
    for (unsigned k = 2; k <= PC; k <<= 1) {
        for (unsigned s = k >> 1; s > 0; s >>= 1) {
            __syncthreads();
            unsigned partner = tid ^ s;
            if (partner > (unsigned)tid) {
                unsigned long long a  = keys[tid];
                unsigned long long bb = keys[partner];
                bool ascending = ((tid & k) == 0);
                if ((a > bb) == ascending) {
                    keys[tid]     = bb;
                    keys[partner] = a;
                }
            }
        }
    }
    __syncthreads();

    if (tid < KK) {
        unsigned long long kv = keys[tid];
        int o = j * KK + tid;
        g_idx[o]  = (int)(unsigned)(kv & 0xffffffffu);
        g_vals[o] = __uint_as_float((unsigned)(kv >> 32));
        out[MASK_OUT_OFF + o] = (float)j;   // mask[idx] == class id by construction
    }
}

// ---------------------------------------------------------------------------
// Kernel 3: X_out[r,:] = X[idx[r],:] * vals[r]   (one block per row, float4)
// ---------------------------------------------------------------------------
__global__ void xout_kernel(const float* __restrict__ X,
                            float* __restrict__ out) {
    int r  = blockIdx.x;
    int ri = g_idx[r];
    float v = g_vals[r];
    const float4* src = (const float4*)(X + (size_t)ri * IN_DIM);
    float4*       dst = (float4*)(out + X_OUT_OFF + (size_t)r * IN_DIM);
    float4 x = src[threadIdx.x];            // 128 threads * 4 = 512 floats
    dst[threadIdx.x] = make_float4(x.x * v, x.y * v, x.z * v, x.w * v);
}

// ---------------------------------------------------------------------------
// Kernel 4: M_out[r,c] = M[idx[r], idx[c]]
// Stage the full 32KB source row in SMEM -> coalesced read AND write.
// One block per output row, 512 threads.
// ---------------------------------------------------------------------------
__global__ __launch_bounds__(512) void mout_kernel(const float* __restrict__ M,
                                                   float* __restrict__ out) {
    __shared__ float row[N];                // 32 KB
    int r  = blockIdx.x;
    int ri = g_idx[r];
    const float4* src = (const float4*)(M + (size_t)ri * N);
    float4* rowv = (float4*)row;
#pragma unroll
    for (int t = threadIdx.x; t < N / 4; t += 512)
        rowv[t] = src[t];
    __syncthreads();
    float* dst = out + M_OUT_OFF + (size_t)r * NSEL;
#pragma unroll
    for (int c = threadIdx.x; c < NSEL; c += 512)
        dst[c] = row[g_idx[c]];
}

// ---------------------------------------------------------------------------
extern "C" void kernel_launch(void* const* d_in, const int* in_sizes, int n_in,
                              void* d_out, int out_size) {
    const float* M    = (const float*)d_in[0];
    const float* X    = (const float*)d_in[1];
    const int*   mask = (const int*)  d_in[2];
    const float* W    = (const float*)d_in[3];
    const float* b    = (const float*)d_in[4];
    float* out = (float*)d_out;

    detect_mask_kernel<<<1, 1>>>(mask);
    score_kernel<<<N / 8, 256>>>(X, W, b);          // 8 warps/block, 1 row/warp
    select_kernel<<<NCLASS, PC>>>(mask, out);
    xout_kernel<<<NSEL, 128>>>(X, out);
    mout_kernel<<<NSEL, 512>>>(M, out);
}

// round 6
// speedup vs baseline: 1.3533x; 1.3533x over previous
#include <cuda_runtime.h>
#include <cuda_bf16.h>
#include <cstdint>

// Problem constants
#define N        8192
#define IN_DIM   512
#define NCLASS   16
#define PC       512      // per class
#define KK       256      // kept per class
#define NSEL     4096     // NCLASS * KK

// Output layout (single f32 buffer): M_out | X_out | mask_out
#define M_OUT_OFF    0
#define X_OUT_OFF    (NSEL * (size_t)NSEL)               // 16777216
#define MASK_OUT_OFF (X_OUT_OFF + NSEL * (size_t)IN_DIM) // 18874368

// Scratch (device globals — no allocation allowed)
__device__ float              g_scores[N];
__device__ int                g_idx[NSEL];
__device__ float              g_vals[NSEL];
__device__ int                g_is64;
__device__ int                g_cnt[NCLASS];
__device__ unsigned long long g_keys[N];

// ---------------------------------------------------------------------------
// Kernel 0: detect int64-layout mask via ballot (odd int32 words all zero),
// and zero the scatter counters. 128 threads, ~1us.
// ---------------------------------------------------------------------------
__global__ void detect_mask_kernel(const int* __restrict__ m) {
    int t = threadIdx.x;                       // 0..127
    int nz = (m[2 * t + 1] != 0);
    unsigned any = __ballot_sync(0xffffffffu, nz);
#pragma unroll
    for (int o = 16; o > 0; o >>= 1)
        any |= __shfl_xor_sync(0xffffffffu, any, o);
    __syncthreads();
    if (t == 0) {
        // reduce across the 4 warps via shared
        __shared__ unsigned acc[4];
        (void)acc;
    }
    // simpler: block-wide OR through shared
    __shared__ unsigned warp_any[4];
    if ((t & 31) == 0) warp_any[t >> 5] = any;
    __syncthreads();
    if (t == 0) {
        unsigned a = warp_any[0] | warp_any[1] | warp_any[2] | warp_any[3];
        g_is64 = (a == 0u) ? 1 : 0;
    }
    if (t < NCLASS) g_cnt[t] = 0;
}

// ---------------------------------------------------------------------------
// Bit-replica of XLA:CPU / Eigen Cephes expf (confirmed: w=0 on R5).
// ---------------------------------------------------------------------------
__device__ __forceinline__ float cephes_expf(float r) {
    float in = fminf(fmaxf(r, -88.3762626647949f), 88.3762626647950f);
    float fx = floorf(__fmaf_rn(in, 1.44269504088896341f, 0.5f));
    float tmp = __fmul_rn(0.693359375f, fx);
    float zz  = __fmul_rn(-2.12194440e-4f, fx);
    float x   = __fsub_rn(__fsub_rn(in, tmp), zz);
    float z2  = __fmul_rn(x, x);
    float y   = __fmaf_rn(x, 1.9875691500E-4f, 1.3981999507E-3f);
    y = __fmaf_rn(y, x, 8.3334519073E-3f);
    y = __fmaf_rn(y, x, 4.1665795894E-2f);
    y = __fmaf_rn(y, x, 1.6666665459E-1f);
    y = __fmaf_rn(y, x, 5.0000001201E-1f);
    y = __fmaf_rn(y, z2, x);
    y = __fadd_rn(1.0f, y);
    int n = (int)fx;
    float pow2n = __int_as_float((unsigned)(n + 127) << 23);
    return __fmul_rn(y, pow2n);
}

// ---------------------------------------------------------------------------
// Kernel 1: scores[i] = 1 / (1 + cephes_exp(-((X[i,:]·W + b) / 100)))
// One warp per row. Dot order irrelevant at score precision (verified).
// ---------------------------------------------------------------------------
__global__ void score_kernel(const float* __restrict__ X,
                             const float* __restrict__ W,
                             const float* __restrict__ b) {
    int warps_per_block = blockDim.x >> 5;
    int row  = blockIdx.x * warps_per_block + (threadIdx.x >> 5);
    int lane = threadIdx.x & 31;
    if (row >= N) return;
    const float* xr = X + (size_t)row * IN_DIM;
    float s = 0.f;
#pragma unroll
    for (int k = lane; k < IN_DIM; k += 32)
        s = __fmaf_rn(xr[k], __ldg(&W[k]), s);
#pragma unroll
    for (int o = 16; o > 0; o >>= 1)
        s += __shfl_xor_sync(0xffffffffu, s, o);
    if (lane == 0) {
        float x = __fdiv_rn(__fadd_rn(s, b[0]), 100.0f);
        float t = cephes_expf(-x);
        g_scores[row] = __fdiv_rn(1.0f, __fadd_rn(1.0f, t));
    }
}

// ---------------------------------------------------------------------------
// Kernel 2a: unordered per-class compaction via atomics. Order within a class
// bucket is irrelevant: the subsequent sort key (score_bits<<32)|idx fully
// determines the final order (ties -> lower idx), matching jax top_k.
// ---------------------------------------------------------------------------
__global__ void scatter_kernel(const int* __restrict__ mask_i32) {
    int i = blockIdx.x * blockDim.x + threadIdx.x;  // 0..N-1
    int cls = g_is64 ? mask_i32[2 * i] : mask_i32[i];
    unsigned sb = __float_as_uint(g_scores[i]);     // (0,1): bit order == value order
    int pos = atomicAdd(&g_cnt[cls], 1);
    g_keys[cls * PC + pos] = ((unsigned long long)sb << 32) | (unsigned)i;
}

// ---------------------------------------------------------------------------
// Kernel 2b: per-class bitonic sort (512), keep 256 smallest.
// One block per class, 512 threads.
// ---------------------------------------------------------------------------
__global__ __launch_bounds__(PC) void sort_kernel(float* __restrict__ out) {
    __shared__ unsigned long long keys[PC];
    const int j   = blockIdx.x;
    const int tid = threadIdx.x;

    keys[tid] = g_keys[j * PC + tid];

    for (unsigned k = 2; k <= PC; k <<= 1) {
        for (unsigned s = k >> 1; s > 0; s >>= 1) {
            __syncthreads();
            unsigned partner = tid ^ s;
            if (partner > (unsigned)tid) {
                unsigned long long a  = keys[tid];
                unsigned long long bb = keys[partner];
                bool ascending = ((tid & k) == 0);
                if ((a > bb) == ascending) {
                    keys[tid]     = bb;
                    keys[partner] = a;
                }
            }
        }
    }
    __syncthreads();

    if (tid < KK) {
        unsigned long long kv = keys[tid];
        int o = j * KK + tid;
        g_idx[o]  = (int)(unsigned)(kv & 0xffffffffu);
        g_vals[o] = __uint_as_float((unsigned)(kv >> 32));
        out[MASK_OUT_OFF + o] = (float)j;   // mask[idx] == class id by construction
    }
}

// ---------------------------------------------------------------------------
// Kernel 3 (fused): per output row r:
//   X_out[r,:] = X[idx[r],:] * vals[r]        (threads < 128, float4)
//   M_out[r,c] = M[idx[r], idx[c]]            (SMEM-staged row, float4 writes)
// One block per row, 512 threads. Reads and writes fully coalesced; the
// column gather is a random SMEM read (conflict-light).
// ---------------------------------------------------------------------------
__global__ __launch_bounds__(512) void moutx_kernel(const float* __restrict__ M,
                                                    const float* __restrict__ X,
                                                    float* __restrict__ out) {
    __shared__ float row[N];                // 32 KB
    const int r  = blockIdx.x;
    const int ri = g_idx[r];

    // Stage the 32KB M source row (coalesced float4)
    const float4* src = (const float4*)(M + (size_t)ri * N);
    float4* rowv = (float4*)row;
#pragma unroll
    for (int t = threadIdx.x; t < N / 4; t += 512)
        rowv[t] = src[t];

    // X row: 128 float4s, overlapped with the M-row loads
    if (threadIdx.x < 128) {
        float v = g_vals[r];
        float4 x = ((const float4*)(X + (size_t)ri * IN_DIM))[threadIdx.x];
        ((float4*)(out + X_OUT_OFF + (size_t)r * IN_DIM))[threadIdx.x] =
            make_float4(x.x * v, x.y * v, x.z * v, x.w * v);
    }
    __syncthreads();

    // Gathered column write, vectorized: 4 columns per float4 store
    float4* dst4 = (float4*)(out + M_OUT_OFF + (size_t)r * NSEL);
    const int4* gi4 = (const int4*)g_idx;
#pragma unroll
    for (int t = threadIdx.x; t < NSEL / 4; t += 512) {
        int4 ii = gi4[t];
        float4 o;
        o.x = row[ii.x];
        o.y = row[ii.y];
        o.z = row[ii.z];
        o.w = row[ii.w];
        dst4[t] = o;
    }
}

// ---------------------------------------------------------------------------
extern "C" void kernel_launch(void* const* d_in, const int* in_sizes, int n_in,
                              void* d_out, int out_size) {
    const float* M    = (const float*)d_in[0];
    const float* X    = (const float*)d_in[1];
    const int*   mask = (const int*)  d_in[2];
    const float* W    = (const float*)d_in[3];
    const float* b    = (const float*)d_in[4];
    float* out = (float*)d_out;

    detect_mask_kernel<<<1, 128>>>(mask);
    score_kernel<<<N / 8, 256>>>(X, W, b);          // 8 warps/block, 1 row/warp
    scatter_kernel<<<N / 256, 256>>>(mask);
    sort_kernel<<<NCLASS, PC>>>(out);
    moutx_kernel<<<NSEL, 512>>>(M, X, out);
}

// round 7
// speedup vs baseline: 1.4122x; 1.0435x over previous
#include <cuda_runtime.h>
#include <cuda_bf16.h>
#include <cstdint>

// Problem constants
#define N        8192
#define IN_DIM   512
#define NCLASS   16
#define PC       512      // per class
#define KK       256      // kept per class
#define NSEL     4096     // NCLASS * KK

// Output layout (single f32 buffer): M_out | X_out | mask_out
#define M_OUT_OFF    0
#define X_OUT_OFF    (NSEL * (size_t)NSEL)               // 16777216
#define MASK_OUT_OFF (X_OUT_OFF + NSEL * (size_t)IN_DIM) // 18874368

// Scratch (device globals — no allocation allowed)
__device__ int                g_idx[NSEL];
__device__ float              g_vals[NSEL];
__device__ int                g_is64;
__device__ int                g_cnt[NCLASS];
__device__ unsigned long long g_keys[N];

// ---------------------------------------------------------------------------
// Kernel 0: detect int64-layout mask (odd int32 words all zero) via ballot,
// and zero the scatter counters.
// ---------------------------------------------------------------------------
__global__ void detect_mask_kernel(const int* __restrict__ m) {
    __shared__ unsigned warp_any[4];
    int t = threadIdx.x;                       // 0..127
    int nz = (m[2 * t + 1] != 0);
    unsigned any = __ballot_sync(0xffffffffu, nz);
    if ((t & 31) == 0) warp_any[t >> 5] = any;
    __syncthreads();
    if (t == 0) {
        unsigned a = warp_any[0] | warp_any[1] | warp_any[2] | warp_any[3];
        g_is64 = (a == 0u) ? 1 : 0;
    }
    if (t < NCLASS) g_cnt[t] = 0;
}

// ---------------------------------------------------------------------------
// Bit-replica of XLA:CPU / Eigen Cephes expf (confirmed bit-exact: R5 w=0).
// ---------------------------------------------------------------------------
__device__ __forceinline__ float cephes_expf(float r) {
    float in = fminf(fmaxf(r, -88.3762626647949f), 88.3762626647950f);
    float fx = floorf(__fmaf_rn(in, 1.44269504088896341f, 0.5f));
    float tmp = __fmul_rn(0.693359375f, fx);
    float zz  = __fmul_rn(-2.12194440e-4f, fx);
    float x   = __fsub_rn(__fsub_rn(in, tmp), zz);
    float z2  = __fmul_rn(x, x);
    float y   = __fmaf_rn(x, 1.9875691500E-4f, 1.3981999507E-3f);
    y = __fmaf_rn(y, x, 8.3334519073E-3f);
    y = __fmaf_rn(y, x, 4.1665795894E-2f);
    y = __fmaf_rn(y, x, 1.6666665459E-1f);
    y = __fmaf_rn(y, x, 5.0000001201E-1f);
    y = __fmaf_rn(y, z2, x);
    y = __fadd_rn(1.0f, y);
    int n = (int)fx;
    float pow2n = __int_as_float((unsigned)(n + 127) << 23);
    return __fmul_rn(y, pow2n);
}

// ---------------------------------------------------------------------------
// Kernel 1 (fused score + scatter): one warp per row computes
//   score = 1/(1 + cephes_exp(-((X·W + b)/100)))
// then lane 0 scatters the packed key (score_bits<<32 | row) into its class
// bucket via atomicAdd. Bucket order is irrelevant (sort key is total).
// ---------------------------------------------------------------------------
__global__ void score_kernel(const float* __restrict__ X,
                             const float* __restrict__ W,
                             const float* __restrict__ b,
                             const int* __restrict__ mask_i32) {
    int warps_per_block = blockDim.x >> 5;
    int row  = blockIdx.x * warps_per_block + (threadIdx.x >> 5);
    int lane = threadIdx.x & 31;
    if (row >= N) return;
    const float* xr = X + (size_t)row * IN_DIM;
    float s = 0.f;
#pragma unroll
    for (int k = lane; k < IN_DIM; k += 32)
        s = __fmaf_rn(xr[k], __ldg(&W[k]), s);
#pragma unroll
    for (int o = 16; o > 0; o >>= 1)
        s += __shfl_xor_sync(0xffffffffu, s, o);
    if (lane == 0) {
        float x = __fdiv_rn(__fadd_rn(s, b[0]), 100.0f);
        float t = cephes_expf(-x);
        float sc = __fdiv_rn(1.0f, __fadd_rn(1.0f, t));
        unsigned sb = __float_as_uint(sc);          // (0,1): bit order == value order
        int cls = g_is64 ? mask_i32[2 * row] : mask_i32[row];
        int pos = atomicAdd(&g_cnt[cls], 1);
        g_keys[cls * PC + pos] = ((unsigned long long)sb << 32) | (unsigned)row;
    }
}

// ---------------------------------------------------------------------------
// Hybrid bitonic sort, 512 keys/class, one block (512 thr) per class.
// Stages with span s<=16 are intra-warp -> register + shfl_xor (no barriers);
// only the 10 cross-warp stages (s>=32) go through SMEM. 14 barriers vs 45.
// ---------------------------------------------------------------------------
__device__ __forceinline__ unsigned long long cex_shfl(unsigned long long v,
                                                       int s, bool asc, int e) {
    unsigned long long o = __shfl_xor_sync(0xffffffffu, v, s);
    bool lower  = (e & s) == 0;
    bool keepMin = (lower == asc);
    return keepMin ? (o < v ? o : v) : (o > v ? o : v);
}

__global__ __launch_bounds__(PC) void sort_kernel(float* __restrict__ out) {
    __shared__ unsigned long long keys[PC];
    const int j   = blockIdx.x;
    const int tid = threadIdx.x;

    unsigned long long v = g_keys[j * PC + tid];

    // k = 2..32: entirely intra-warp
#pragma unroll
    for (unsigned k = 2; k <= 32; k <<= 1) {
        bool asc = ((tid & k) == 0);
        for (int s = k >> 1; s >= 1; s >>= 1)
            v = cex_shfl(v, s, asc, tid);
    }
    keys[tid] = v;

    // k = 64..512: cross-warp stages in SMEM, tail (s<=16) in registers
#pragma unroll
    for (unsigned k = 64; k <= PC; k <<= 1) {
        for (unsigned s = k >> 1; s >= 32; s >>= 1) {
            __syncthreads();
            unsigned partner = tid ^ s;
            if (partner > (unsigned)tid) {
                unsigned long long a  = keys[tid];
                unsigned long long bb = keys[partner];
                bool ascending = ((tid & k) == 0);
                if ((a > bb) == ascending) {
                    keys[tid]     = bb;
                    keys[partner] = a;
                }
            }
        }
        __syncthreads();
        v = keys[tid];
        bool asc = ((tid & k) == 0);
#pragma unroll
        for (int s = 16; s >= 1; s >>= 1)
            v = cex_shfl(v, s, asc, tid);
        keys[tid] = v;
    }

    // v now holds the sorted element at rank tid
    if (tid < KK) {
        int o = j * KK + tid;
        g_idx[o]  = (int)(unsigned)(v & 0xffffffffu);
        g_vals[o] = __uint_as_float((unsigned)(v >> 32));
        out[MASK_OUT_OFF + o] = (float)j;   // mask[idx] == class id by construction
    }
}

// ---------------------------------------------------------------------------
// Kernel 3 (fused): per output row r:
//   X_out[r,:] = X[idx[r],:] * vals[r]        (threads < 128, float4)
//   M_out[r,c] = M[idx[r], idx[c]]            (SMEM-staged row, float4 writes)
// ---------------------------------------------------------------------------
__global__ __launch_bounds__(512) void moutx_kernel(const float* __restrict__ M,
                                                    const float* __restrict__ X,
                                                    float* __restrict__ out) {
    __shared__ float row[N];                // 32 KB
    const int r  = blockIdx.x;
    const int ri = g_idx[r];

    const float4* src = (const float4*)(M + (size_t)ri * N);
    float4* rowv = (float4*)row;
#pragma unroll
    for (int t = threadIdx.x; t < N / 4; t += 512)
        rowv[t] = src[t];

    if (threadIdx.x < 128) {
        float v = g_vals[r];
        float4 x = ((const float4*)(X + (size_t)ri * IN_DIM))[threadIdx.x];
        ((float4*)(out + X_OUT_OFF + (size_t)r * IN_DIM))[threadIdx.x] =
            make_float4(x.x * v, x.y * v, x.z * v, x.w * v);
    }
    __syncthreads();

    float4* dst4 = (float4*)(out + M_OUT_OFF + (size_t)r * NSEL);
    const int4* gi4 = (const int4*)g_idx;
#pragma unroll
    for (int t = threadIdx.x; t < NSEL / 4; t += 512) {
        int4 ii = gi4[t];
        float4 o;
        o.x = row[ii.x];
        o.y = row[ii.y];
        o.z = row[ii.z];
        o.w = row[ii.w];
        dst4[t] = o;
    }
}

// ---------------------------------------------------------------------------
extern "C" void kernel_launch(void* const* d_in, const int* in_sizes, int n_in,
                              void* d_out, int out_size) {
    const float* M    = (const float*)d_in[0];
    const float* X    = (const float*)d_in[1];
    const int*   mask = (const int*)  d_in[2];
    const float* W    = (const float*)d_in[3];
    const float* b    = (const float*)d_in[4];
    float* out = (float*)d_out;

    detect_mask_kernel<<<1, 128>>>(mask);
    score_kernel<<<N / 8, 256>>>(X, W, b, mask);    // 8 warps/block, 1 row/warp
    sort_kernel<<<NCLASS, PC>>>(out);
    moutx_kernel<<<NSEL, 512>>>(M, X, out);
}

// round 8
// speedup vs baseline: 1.4609x; 1.0345x over previous
#include <cuda_runtime.h>
#include <cuda_bf16.h>
#include <cstdint>

// Problem constants
#define N        8192
#define IN_DIM   512
#define NCLASS   16
#define PC       512      // per class
#define KK       256      // kept per class
#define NSEL     4096     // NCLASS * KK

// Output layout (single f32 buffer): M_out | X_out | mask_out
#define M_OUT_OFF    0
#define X_OUT_OFF    (NSEL * (size_t)NSEL)               // 16777216
#define MASK_OUT_OFF (X_OUT_OFF + NSEL * (size_t)IN_DIM) // 18874368

// Scratch (device globals — no allocation allowed)
__device__ int                g_idx[NSEL];
__device__ float              g_vals[NSEL];
__device__ unsigned           g_cnt[NCLASS];   // monotone; pos = old & 511
__device__ unsigned long long g_keys[N];

// ---------------------------------------------------------------------------
// Bit-replica of XLA:CPU / Eigen Cephes expf (confirmed bit-exact: R5 w=0).
// ---------------------------------------------------------------------------
__device__ __forceinline__ float cephes_expf(float r) {
    float in = fminf(fmaxf(r, -88.3762626647949f), 88.3762626647950f);
    float fx = floorf(__fmaf_rn(in, 1.44269504088896341f, 0.5f));
    float tmp = __fmul_rn(0.693359375f, fx);
    float zz  = __fmul_rn(-2.12194440e-4f, fx);
    float x   = __fsub_rn(__fsub_rn(in, tmp), zz);
    float z2  = __fmul_rn(x, x);
    float y   = __fmaf_rn(x, 1.9875691500E-4f, 1.3981999507E-3f);
    y = __fmaf_rn(y, x, 8.3334519073E-3f);
    y = __fmaf_rn(y, x, 4.1665795894E-2f);
    y = __fmaf_rn(y, x, 1.6666665459E-1f);
    y = __fmaf_rn(y, x, 5.0000001201E-1f);
    y = __fmaf_rn(y, z2, x);
    y = __fadd_rn(1.0f, y);
    int n = (int)fx;
    float pow2n = __int_as_float((unsigned)(n + 127) << 23);
    return __fmul_rn(y, pow2n);
}

// ---------------------------------------------------------------------------
// Kernel 1 (fused detect + score + scatter), one warp per row (8 rows/block).
//   - block-local is64 detection: ballot over the first 128 odd int32 words
//     (all zero iff mask arrived as int64). L2-cached after the first block.
//   - score = 1/(1 + cephes_exp(-((X·W + b)/100)))
//   - lane 0 scatters (score_bits<<32 | row) into its class bucket. Slot =
//     atomicAdd & 511: each run adds exactly 512/class, so the counter stays
//     a multiple of 512 across graph replays -> deterministic slots.
// ---------------------------------------------------------------------------
__global__ void score_kernel(const float* __restrict__ X,
                             const float* __restrict__ W,
                             const float* __restrict__ b,
                             const int* __restrict__ mask_i32) {
    __shared__ unsigned warp_any[8];
    __shared__ int s_is64;

    const int t    = threadIdx.x;          // 0..255
    const int wid  = t >> 5;
    const int lane = t & 31;

    // --- embedded is64 detection (uses t%128 -> first 128 int64 entries) ---
    int nz = (mask_i32[2 * (t & 127) + 1] != 0);
    unsigned any = __ballot_sync(0xffffffffu, nz);
    if (lane == 0) warp_any[wid] = any;
    __syncthreads();
    if (t == 0) {
        unsigned a = 0;
#pragma unroll
        for (int w = 0; w < 8; ++w) a |= warp_any[w];
        s_is64 = (a == 0u) ? 1 : 0;
    }
    __syncthreads();
    const int is64 = s_is64;

    // --- score ---
    const int row = blockIdx.x * 8 + wid;
    const float* xr = X + (size_t)row * IN_DIM;
    float s = 0.f;
#pragma unroll
    for (int k = lane; k < IN_DIM; k += 32)
        s = __fmaf_rn(xr[k], __ldg(&W[k]), s);
#pragma unroll
    for (int o = 16; o > 0; o >>= 1)
        s += __shfl_xor_sync(0xffffffffu, s, o);

    if (lane == 0) {
        float x  = __fdiv_rn(__fadd_rn(s, b[0]), 100.0f);
        float tt = cephes_expf(-x);
        float sc = __fdiv_rn(1.0f, __fadd_rn(1.0f, tt));
        unsigned sb = __float_as_uint(sc);          // (0,1): bit order == value order
        int cls = is64 ? mask_i32[2 * row] : mask_i32[row];
        unsigned pos = atomicAdd(&g_cnt[cls], 1u) & (PC - 1);
        g_keys[cls * PC + pos] = ((unsigned long long)sb << 32) | (unsigned)row;
    }
}

// ---------------------------------------------------------------------------
// Hybrid bitonic sort, 512 keys/class, one block (512 thr) per class.
// Intra-warp spans via shfl_xor (no barriers); 10 cross-warp stages in SMEM.
// ---------------------------------------------------------------------------
__device__ __forceinline__ unsigned long long cex_shfl(unsigned long long v,
                                                       int s, bool asc, int e) {
    unsigned long long o = __shfl_xor_sync(0xffffffffu, v, s);
    bool lower   = (e & s) == 0;
    bool keepMin = (lower == asc);
    return keepMin ? (o < v ? o : v) : (o > v ? o : v);
}

__global__ __launch_bounds__(PC) void sort_kernel(float* __restrict__ out) {
    __shared__ unsigned long long keys[PC];
    const int j   = blockIdx.x;
    const int tid = threadIdx.x;

    unsigned long long v = g_keys[j * PC + tid];

#pragma unroll
    for (unsigned k = 2; k <= 32; k <<= 1) {
        bool asc = ((tid & k) == 0);
        for (int s = k >> 1; s >= 1; s >>= 1)
            v = cex_shfl(v, s, asc, tid);
    }
    keys[tid] = v;

#pragma unroll
    for (unsigned k = 64; k <= PC; k <<= 1) {
        for (unsigned s = k >> 1; s >= 32; s >>= 1) {
            __syncthreads();
            unsigned partner = tid ^ s;
            if (partner > (unsigned)tid) {
                unsigned long long a  = keys[tid];
                unsigned long long bb = keys[partner];
                bool ascending = ((tid & k) == 0);
                if ((a > bb) == ascending) {
                    keys[tid]     = bb;
                    keys[partner] = a;
                }
            }
        }
        __syncthreads();
        v = keys[tid];
        bool asc = ((tid & k) == 0);
#pragma unroll
        for (int s = 16; s >= 1; s >>= 1)
            v = cex_shfl(v, s, asc, tid);
        keys[tid] = v;
    }

    if (tid < KK) {
        int o = j * KK + tid;
        g_idx[o]  = (int)(unsigned)(v & 0xffffffffu);
        g_vals[o] = __uint_as_float((unsigned)(v >> 32));
        out[MASK_OUT_OFF + o] = (float)j;   // mask[idx] == class id by construction
    }
}

// ---------------------------------------------------------------------------
// cp.async helpers
// ---------------------------------------------------------------------------
__device__ __forceinline__ void cp_async16(uint32_t saddr, const void* gptr) {
    asm volatile("cp.async.cg.shared.global [%0], [%1], 16;\n"
                 :: "r"(saddr), "l"(gptr));
}
__device__ __forceinline__ void cp_commit() {
    asm volatile("cp.async.commit_group;\n");
}
template <int NN>
__device__ __forceinline__ void cp_wait() {
    asm volatile("cp.async.wait_group %0;\n" :: "n"(NN));
}

// ---------------------------------------------------------------------------
// Kernel 3 (fused, pipelined): 4 output rows per block, double-buffered
// cp.async row staging so row k+1's DRAM loads overlap row k's gather.
//   X_out[r,:] = X[idx[r],:] * vals[r]
//   M_out[r,c] = M[idx[r], idx[c]]
// 512 threads; dynamic SMEM = 2 * 32KB.
// ---------------------------------------------------------------------------
#define MROWS 4
extern __shared__ float s_buf[];   // [2][N]

__device__ __forceinline__ void issue_row(const float* __restrict__ M,
                                          int ri, int bufsel) {
    uint32_t sbase = (uint32_t)__cvta_generic_to_shared(&s_buf[bufsel * N]);
    const char* g = (const char*)(M + (size_t)ri * N);
    int t = threadIdx.x;
#pragma unroll
    for (int i = 0; i < 4; ++i) {
        int off16 = (t + i * 512) * 16;
        cp_async16(sbase + off16, g + off16);
    }
    cp_commit();
}

__device__ __forceinline__ void gather_row(float* __restrict__ out,
                                           int r, int bufsel) {
    const float* row = &s_buf[bufsel * N];
    float4* dst4 = (float4*)(out + M_OUT_OFF + (size_t)r * NSEL);
    const int4* gi4 = (const int4*)g_idx;
#pragma unroll
    for (int i = 0; i < 2; ++i) {
        int t = threadIdx.x + i * 512;
        int4 ii = gi4[t];
        float4 o;
        o.x = row[ii.x];
        o.y = row[ii.y];
        o.z = row[ii.z];
        o.w = row[ii.w];
        dst4[t] = o;
    }
}

__global__ __launch_bounds__(512) void moutx_kernel(const float* __restrict__ M,
                                                    const float* __restrict__ X,
                                                    float* __restrict__ out) {
    const int r0 = blockIdx.x * MROWS;
    const int t  = threadIdx.x;

    int ri0 = g_idx[r0 + 0];
    int ri1 = g_idx[r0 + 1];
    int ri2 = g_idx[r0 + 2];
    int ri3 = g_idx[r0 + 3];

    issue_row(M, ri0, 0);              // group 0
    issue_row(M, ri1, 1);              // group 1

    // X rows (one float4 per thread covers all 4 rows), overlaps the loads
    {
        int xr  = t >> 7;              // 0..3
        int col = t & 127;
        int r   = r0 + xr;
        float v = g_vals[r];
        float4 x = ((const float4*)(X + (size_t)g_idx[r] * IN_DIM))[col];
        ((float4*)(out + X_OUT_OFF + (size_t)r * IN_DIM))[col] =
            make_float4(x.x * v, x.y * v, x.z * v, x.w * v);
    }

    cp_wait<1>(); __syncthreads();
    gather_row(out, r0 + 0, 0);
    __syncthreads();
    issue_row(M, ri2, 0);              // group 2

    cp_wait<1>(); __syncthreads();
    gather_row(out, r0 + 1, 1);
    __syncthreads();
    issue_row(M, ri3, 1);              // group 3

    cp_wait<1>(); __syncthreads();
    gather_row(out, r0 + 2, 0);

    cp_wait<0>(); __syncthreads();
    gather_row(out, r0 + 3, 1);
    (void)ri0; (void)ri1;
}

// ---------------------------------------------------------------------------
extern "C" void kernel_launch(void* const* d_in, const int* in_sizes, int n_in,
                              void* d_out, int out_size) {
    const float* M    = (const float*)d_in[0];
    const float* X    = (const float*)d_in[1];
    const int*   mask = (const int*)  d_in[2];
    const float* W    = (const float*)d_in[3];
    const float* b    = (const float*)d_in[4];
    float* out = (float*)d_out;

    static const size_t MOUT_SMEM = 2 * N * sizeof(float);   // 64 KB
    cudaFuncSetAttribute(moutx_kernel,
                         cudaFuncAttributeMaxDynamicSharedMemorySize,
                         (int)MOUT_SMEM);

    score_kernel<<<N / 8, 256>>>(X, W, b, mask);
    sort_kernel<<<NCLASS, PC>>>(out);
    moutx_kernel<<<NSEL / MROWS, 512, MOUT_SMEM>>>(M, X, out);
}